// round 1
// baseline (speedup 1.0000x reference)
#include <cuda_runtime.h>
#include <cuda_bf16.h>
#include <cstdint>

// Problem constants
#define BH_    64
#define LQ_    1024
#define LK_    1024
#define DD_    64
#define TQ_    32          // queries per CTA
#define TKK_   256         // K rows per phase-2 tile
#define SKPAD  68          // smem row stride (floats) for K/V tiles (mult of 4 for float4)
#define SQPAD  68          // smem row stride for Q tile
#define NTHREADS 256

// smem layout (floats):
//   Pbuf : TQ_*LK_            = 32768  (131072 B)
//   Qs   : TQ_*SQPAD          = 2176
//   KVs  : TKK_*SKPAD         = 17408
#define SMEM_FLOATS (32768 + TQ_*SQPAD + TKK_*SKPAD)
#define SMEM_BYTES  (SMEM_FLOATS * 4)

typedef unsigned long long ull;

__device__ __forceinline__ ull pk2(float x, float y) {
    ull u;
    asm("mov.b64 %0, {%1, %2};" : "=l"(u) : "f"(x), "f"(y));
    return u;
}
__device__ __forceinline__ float2 upk2(ull u) {
    float2 r;
    asm("mov.b64 {%0, %1}, %2;" : "=f"(r.x), "=f"(r.y) : "l"(u));
    return r;
}
// packed dual fp32 FMA (Blackwell f32x2 pipe): d = a*b + d, lanewise
__device__ __forceinline__ void fma2(ull& d, ull a, ull b) {
    asm volatile("fma.rn.f32x2 %0, %1, %2, %0;" : "+l"(d) : "l"(a), "l"(b));
}

__global__ void __launch_bounds__(NTHREADS, 1)
attention_fused_kernel(const float* __restrict__ Qg,
                       const float* __restrict__ Kg,
                       const float* __restrict__ Vg,
                       const int*   __restrict__ Mg,
                       const float* __restrict__ QMg,
                       float* __restrict__ out_o,    // may be null
                       float* __restrict__ out_a)    // may be null
{
    extern __shared__ float smem[];
    float* Pbuf = smem;                       // [TQ_][LK_]
    float* Qs   = smem + TQ_ * LK_;           // [TQ_][SQPAD]
    float* KVs  = Qs + TQ_ * SQPAD;           // [TKK_][SKPAD]

    const int tid  = threadIdx.x;
    const int lane = tid & 31;
    const int wid  = tid >> 5;                // 0..7
    const int bh   = blockIdx.y;              // 0..63
    const int q0   = blockIdx.x * TQ_;        // query tile start

    const float* Qrow = Qg + ((size_t)bh * LQ_ + q0) * DD_;
    const float* Kbh  = Kg + (size_t)bh * LK_ * DD_;
    const float* Vbh  = Vg + (size_t)bh * LK_ * DD_;

    // ---------------- load Q tile (scaled by 1/sqrt(64) = 0.125) ----------------
    // TQ_*DD_ = 2048 floats = 512 float4; 2 per thread
    {
        #pragma unroll
        for (int it = 0; it < 2; ++it) {
            int idx = tid + it * NTHREADS;        // 0..511
            int r = idx >> 4;                      // /16 float4 per row
            int c4 = idx & 15;
            float4 v = *(const float4*)(Qrow + r * DD_ + c4 * 4);
            v.x *= 0.125f; v.y *= 0.125f; v.z *= 0.125f; v.w *= 0.125f;
            *(float4*)(&Qs[r * SQPAD + c4 * 4]) = v;
        }
    }

    // ---------------- phase 2: S = (Q/8) K^T  with mask, into Pbuf ----------------
    // thread tile: 4 q rows (warp-uniform) x 8 k columns, f32x2 packed over d
    const int qt = wid;       // warp w handles rows 4w..4w+3
    const int kt = lane;      // k = kt + 32*j

    const int* Mbase = Mg + ((size_t)bh * LQ_ + q0) * LK_;

    #pragma unroll 1
    for (int kb = 0; kb < LK_ / TKK_; ++kb) {
        const int k0 = kb * TKK_;
        __syncthreads();   // previous compute done / Q stores visible
        // load K tile: TKK_ rows x 64 floats = 4096 float4, 16 per thread
        #pragma unroll
        for (int it = 0; it < 16; ++it) {
            int idx = tid + it * NTHREADS;
            int r = idx >> 4;
            int c4 = idx & 15;
            *(float4*)(&KVs[r * SKPAD + c4 * 4]) =
                *(const float4*)(Kbh + (size_t)(k0 + r) * DD_ + c4 * 4);
        }
        __syncthreads();

        ull acc[32];
        #pragma unroll
        for (int t = 0; t < 32; ++t) acc[t] = 0ull;

        #pragma unroll 4
        for (int d = 0; d < DD_; d += 4) {
            ull q01[4], q23[4];
            #pragma unroll
            for (int i = 0; i < 4; ++i) {
                float4 qv = *(float4*)(&Qs[(4 * qt + i) * SQPAD + d]);
                q01[i] = pk2(qv.x, qv.y);
                q23[i] = pk2(qv.z, qv.w);
            }
            #pragma unroll
            for (int j = 0; j < 8; ++j) {
                float4 kv = *(float4*)(&KVs[(kt + 32 * j) * SKPAD + d]);
                ull k01 = pk2(kv.x, kv.y);
                ull k23 = pk2(kv.z, kv.w);
                #pragma unroll
                for (int i = 0; i < 4; ++i) {
                    fma2(acc[i * 8 + j], q01[i], k01);
                    fma2(acc[i * 8 + j], q23[i], k23);
                }
            }
        }

        // apply mask + write scores into Pbuf
        #pragma unroll
        for (int i = 0; i < 4; ++i) {
            const int q = 4 * qt + i;
            const int* mrow = Mbase + (size_t)q * LK_ + k0;
            #pragma unroll
            for (int j = 0; j < 8; ++j) {
                int k = kt + 32 * j;
                float2 f = upk2(acc[i * 8 + j]);
                float s = f.x + f.y;
                s = (mrow[k] == 0) ? -1.0e9f : s;
                Pbuf[q * LK_ + k0 + k] = s;
            }
        }
    }

    // ---------------- phase 3: per-row softmax * query_mask (warp-local rows) ----------------
    {
        #pragma unroll 1
        for (int i = 0; i < 4; ++i) {
            const int q = 4 * qt + i;
            float4* row4 = (float4*)(&Pbuf[q * LK_]);
            float mx = -3.0e38f;
            #pragma unroll
            for (int c = 0; c < 8; ++c) {
                float4 v = row4[lane + 32 * c];
                mx = fmaxf(mx, fmaxf(fmaxf(v.x, v.y), fmaxf(v.z, v.w)));
            }
            #pragma unroll
            for (int o = 16; o > 0; o >>= 1)
                mx = fmaxf(mx, __shfl_xor_sync(0xffffffffu, mx, o));

            float sum = 0.f;
            #pragma unroll
            for (int c = 0; c < 8; ++c) {
                float4 v = row4[lane + 32 * c];
                v.x = __expf(v.x - mx);
                v.y = __expf(v.y - mx);
                v.z = __expf(v.z - mx);
                v.w = __expf(v.w - mx);
                row4[lane + 32 * c] = v;
                sum += (v.x + v.y) + (v.z + v.w);
            }
            #pragma unroll
            for (int o = 16; o > 0; o >>= 1)
                sum += __shfl_xor_sync(0xffffffffu, sum, o);

            const float qm = QMg[(size_t)bh * LQ_ + q0 + q];
            const float sc = qm / sum;

            float4* arow4 = out_a ?
                (float4*)(out_a + ((size_t)bh * LQ_ + q0 + q) * LK_) : nullptr;
            #pragma unroll
            for (int c = 0; c < 8; ++c) {
                float4 v = row4[lane + 32 * c];
                v.x *= sc; v.y *= sc; v.z *= sc; v.w *= sc;
                row4[lane + 32 * c] = v;
                if (arow4) arow4[lane + 32 * c] = v;
            }
        }
    }

    // ---------------- phase 4: O = P @ V ----------------
    // warp w owns rows 4w..4w+3; lane owns d = {2*lane, 2*lane+1} as one f32x2
    ull oacc[4] = {0ull, 0ull, 0ull, 0ull};

    #pragma unroll 1
    for (int kb = 0; kb < LK_ / 64; ++kb) {
        __syncthreads();   // previous V-tile consumers done (also covers first-iter KVs reuse)
        // load V tile: 64 rows x 64 floats = 1024 float4, 4 per thread
        #pragma unroll
        for (int it = 0; it < 4; ++it) {
            int idx = tid + it * NTHREADS;
            int r = idx >> 4;
            int c4 = idx & 15;
            *(float4*)(&KVs[r * SKPAD + c4 * 4]) =
                *(const float4*)(Vbh + (size_t)(kb * 64 + r) * DD_ + c4 * 4);
        }
        __syncthreads();

        #pragma unroll 4
        for (int k = 0; k < 64; k += 4) {
            float4 p[4];
            #pragma unroll
            for (int i = 0; i < 4; ++i)
                p[i] = *(float4*)(&Pbuf[(4 * qt + i) * LK_ + kb * 64 + k]);
            #pragma unroll
            for (int kk = 0; kk < 4; ++kk) {
                float2 v2 = *(float2*)(&KVs[(k + kk) * SKPAD + 2 * lane]);
                ull vv = pk2(v2.x, v2.y);
                #pragma unroll
                for (int i = 0; i < 4; ++i) {
                    float pv = (kk == 0) ? p[i].x : (kk == 1) ? p[i].y
                             : (kk == 2) ? p[i].z : p[i].w;
                    fma2(oacc[i], pk2(pv, pv), vv);
                }
            }
        }
    }

    if (out_o) {
        float* Orow = out_o + ((size_t)bh * LQ_ + q0) * DD_;
        #pragma unroll
        for (int i = 0; i < 4; ++i) {
            float2 r = upk2(oacc[i]);
            *(float2*)(&Orow[(4 * qt + i) * DD_ + 2 * lane]) = r;
        }
    }
}

extern "C" void kernel_launch(void* const* d_in, const int* in_sizes, int n_in,
                              void* d_out, int out_size)
{
    const float* q  = (const float*)d_in[0];
    const float* k  = (const float*)d_in[1];
    const float* v  = (const float*)d_in[2];
    const int*   m  = (const int*)d_in[3];
    const float* qm = (const float*)d_in[4];

    const long long NO = (long long)BH_ * LQ_ * DD_;   //  4,194,304
    const long long NA = (long long)BH_ * LQ_ * LK_;   // 67,108,864

    float* out_o = nullptr;
    float* out_a = nullptr;
    if ((long long)out_size >= NO + NA) {
        out_o = (float*)d_out;
        out_a = (float*)d_out + NO;
    } else if ((long long)out_size == NA) {
        out_a = (float*)d_out;
    } else {
        out_o = (float*)d_out;
    }

    cudaFuncSetAttribute(attention_fused_kernel,
                         cudaFuncAttributeMaxDynamicSharedMemorySize, SMEM_BYTES);

    dim3 grid(LQ_ / TQ_, BH_);   // (32, 64) — x fastest => same-bh CTAs adjacent (L2 reuse of K/V)
    dim3 block(NTHREADS);
    attention_fused_kernel<<<grid, block, SMEM_BYTES>>>(q, k, v, m, qm, out_o, out_a);
}

// round 3
// speedup vs baseline: 1.5560x; 1.5560x over previous
#include <cuda_runtime.h>
#include <cstdint>

#define BH_   64
#define LQ_   1024
#define LK_   1024
#define DD_   64
#define TQ_   32
#define NT    256
#define KTILE 128
#define SKP   68      // K/V smem row stride (floats)
#define SQP   76      // Q smem row stride (fits +8-float swizzle)
#define PSTR  1025    // Pbuf row stride (odd => conflict-free column reads)
#define KHALF (KTILE*SKP)

#define SMEM_FLOATS (TQ_*PSTR + TQ_*SQP + 2*KHALF)
#define SMEM_BYTES  (SMEM_FLOATS*4)

typedef unsigned long long ull;

__device__ __forceinline__ void fma2(ull& d, ull a, ull b) {
    asm volatile("fma.rn.f32x2 %0, %1, %2, %0;" : "+l"(d) : "l"(a), "l"(b));
}
__device__ __forceinline__ ull splat2(float x) {
    ull u; asm("mov.b64 %0, {%1, %1};" : "=l"(u) : "f"(x)); return u;
}
__device__ __forceinline__ float2 upk2(ull u) {
    float2 r; asm("mov.b64 {%0, %1}, %2;" : "=f"(r.x), "=f"(r.y) : "l"(u)); return r;
}
// 16B shared load straight into two f32x2 register pairs
__device__ __forceinline__ void lds_2x64(ull& a, ull& b, const float* p) {
    uint32_t s = (uint32_t)__cvta_generic_to_shared(p);
    asm volatile("ld.shared.v2.b64 {%0, %1}, [%2];" : "=l"(a), "=l"(b) : "r"(s));
}
__device__ __forceinline__ void cp16(float* dst, const float* src) {
    uint32_t s = (uint32_t)__cvta_generic_to_shared(dst);
    asm volatile("cp.async.cg.shared.global [%0], [%1], 16;" :: "r"(s), "l"(src));
}
__device__ __forceinline__ void cp_commit() { asm volatile("cp.async.commit_group;"); }
__device__ __forceinline__ void cp_wait0() { asm volatile("cp.async.wait_group 0;"); }
__device__ __forceinline__ void cp_wait1() { asm volatile("cp.async.wait_group 1;"); }

// load one 128-row x 64-col fp32 tile global->shared via cp.async
__device__ __forceinline__ void prefetch_tile(const float* __restrict__ g, float* s, int tid) {
    #pragma unroll
    for (int it = 0; it < 8; ++it) {
        int idx = tid + it * NT;
        int r   = idx >> 4;
        int c4  = idx & 15;
        cp16(s + r * SKP + c4 * 4, g + r * DD_ + c4 * 4);
    }
}

__global__ void __launch_bounds__(NT, 1)
attention_fused_kernel(const float* __restrict__ Qg,
                       const float* __restrict__ Kg,
                       const float* __restrict__ Vg,
                       const int*   __restrict__ Mg,
                       const float* __restrict__ QMg,
                       float* __restrict__ out_o,
                       float* __restrict__ out_a)
{
    extern __shared__ float smem[];
    float* Pbuf = smem;                          // [32][PSTR]
    float* Qs   = smem + TQ_ * PSTR;             // [32][SQP] (+row swizzle)
    float* KV   = Qs + TQ_ * SQP;                // [2][KTILE][SKP]

    const int tid  = threadIdx.x;
    const int lane = tid & 31;
    const int wid  = tid >> 5;
    const int bh   = blockIdx.y;
    const int q0   = blockIdx.x * TQ_;

    const float* Qrow = Qg + ((size_t)bh * LQ_ + q0) * DD_;
    const float* Kbh  = Kg + (size_t)bh * LK_ * DD_;
    const float* Vbh  = Vg + (size_t)bh * LK_ * DD_;

    // kick off K tile 0 and 1 loads immediately (async)
    prefetch_tile(Kbh,                KV,         tid); cp_commit();
    prefetch_tile(Kbh + KTILE * DD_,  KV + KHALF, tid); cp_commit();

    // ---- load Q (scaled by 1/8) into swizzled smem ----
    #pragma unroll
    for (int it = 0; it < 2; ++it) {
        int idx = tid + it * NT;       // 0..511
        int r = idx >> 4;
        int c4 = idx & 15;
        float4 v = *(const float4*)(Qrow + r * DD_ + c4 * 4);
        v.x *= 0.125f; v.y *= 0.125f; v.z *= 0.125f; v.w *= 0.125f;
        *(float4*)(&Qs[r * SQP + ((r >> 3) & 1) * 8 + c4 * 4]) = v;
    }

    // ---------------- phase 2: S = (Q/8) K^T into Pbuf ----------------
    // warp = (qh, kg): 16 q rows x 32 k cols of the 128-k tile
    // lane = (ql, kl): per-lane 4q x 4k (k strided by 8)
    const int qh = wid >> 2;
    const int kg = wid & 3;
    const int ql = lane >> 3;
    const int kl = lane & 7;
    const int qbase = qh * 16 + ql * 4;
    const int qswz  = ((qbase >> 3) & 1) * 8;    // constant per thread
    const int krow0 = kg * 32 + kl;              // FIX: include warp's k-group offset

    #pragma unroll 1
    for (int t = 0; t < 8; ++t) {
        cp_wait1();            // tile t resident (t+1 may still be in flight)
        __syncthreads();

        const float* Kt = KV + (t & 1) * KHALF;

        ull acc[4][4];
        #pragma unroll
        for (int i = 0; i < 4; ++i)
            #pragma unroll
            for (int j = 0; j < 4; ++j) acc[i][j] = 0ull;

        #pragma unroll 4
        for (int d = 0; d < DD_; d += 4) {
            ull q01[4], q23[4], k01[4], k23[4];
            #pragma unroll
            for (int i = 0; i < 4; ++i)
                lds_2x64(q01[i], q23[i], Qs + (qbase + i) * SQP + qswz + d);
            #pragma unroll
            for (int j = 0; j < 4; ++j)
                lds_2x64(k01[j], k23[j], Kt + (krow0 + j * 8) * SKP + d);
            #pragma unroll
            for (int i = 0; i < 4; ++i)
                #pragma unroll
                for (int j = 0; j < 4; ++j) {
                    fma2(acc[i][j], q01[i], k01[j]);
                    fma2(acc[i][j], q23[i], k23[j]);
                }
        }

        // writeback raw scores (mask applied in phase 3)
        #pragma unroll
        for (int i = 0; i < 4; ++i) {
            float* prow = Pbuf + (qbase + i) * PSTR + t * KTILE + krow0;
            #pragma unroll
            for (int j = 0; j < 4; ++j) {
                float2 f = upk2(acc[i][j]);
                prow[j * 8] = f.x + f.y;
            }
        }

        __syncthreads();       // tile t fully consumed before its buffer is overwritten
        if (t + 2 < 8) {
            prefetch_tile(Kbh + (size_t)(t + 2) * KTILE * DD_, KV + (t & 1) * KHALF, tid);
        } else {
            // start streaming V tiles 0/1 — loads hide under the softmax phase
            prefetch_tile(Vbh + (size_t)(t + 2 - 8) * KTILE * DD_, KV + (t & 1) * KHALF, tid);
        }
        cp_commit();
    }

    // ---------------- phase 3: mask + softmax * query_mask ----------------
    #pragma unroll 1
    for (int i = 0; i < 4; ++i) {
        const int q = wid * 4 + i;
        const int4* mrow = (const int4*)(Mg + ((size_t)bh * LQ_ + q0 + q) * LK_);
        int4  m[8];
        float s[32];
        #pragma unroll
        for (int c = 0; c < 8; ++c) m[c] = mrow[c * 32 + lane];
        #pragma unroll
        for (int c = 0; c < 8; ++c) {
            const float* pr = Pbuf + q * PSTR + (c * 32 + lane) * 4;
            s[4*c+0] = pr[0]; s[4*c+1] = pr[1]; s[4*c+2] = pr[2]; s[4*c+3] = pr[3];
        }
        #pragma unroll
        for (int c = 0; c < 8; ++c) {
            if (m[c].x == 0) s[4*c+0] = -1.0e9f;
            if (m[c].y == 0) s[4*c+1] = -1.0e9f;
            if (m[c].z == 0) s[4*c+2] = -1.0e9f;
            if (m[c].w == 0) s[4*c+3] = -1.0e9f;
        }
        float mx = -3.0e38f;
        #pragma unroll
        for (int t2 = 0; t2 < 32; ++t2) mx = fmaxf(mx, s[t2]);
        #pragma unroll
        for (int o = 16; o > 0; o >>= 1)
            mx = fmaxf(mx, __shfl_xor_sync(0xffffffffu, mx, o));

        float sum = 0.f;
        #pragma unroll
        for (int t2 = 0; t2 < 32; ++t2) { s[t2] = __expf(s[t2] - mx); sum += s[t2]; }
        #pragma unroll
        for (int o = 16; o > 0; o >>= 1)
            sum += __shfl_xor_sync(0xffffffffu, sum, o);

        const float sc = QMg[(size_t)bh * LQ_ + q0 + q] / sum;

        float* arow = out_a ? (out_a + ((size_t)bh * LQ_ + q0 + q) * LK_) : nullptr;
        #pragma unroll
        for (int c = 0; c < 8; ++c) {
            int kbase = (c * 32 + lane) * 4;
            float4 o4;
            o4.x = s[4*c+0] * sc; o4.y = s[4*c+1] * sc;
            o4.z = s[4*c+2] * sc; o4.w = s[4*c+3] * sc;
            float* pr = Pbuf + q * PSTR + kbase;
            pr[0] = o4.x; pr[1] = o4.y; pr[2] = o4.z; pr[3] = o4.w;
            if (arow) *(float4*)(arow + kbase) = o4;
        }
    }

    // ---------------- phase 4: O = P @ V ----------------
    // lane owns q = lane (P column reads conflict-free: stride PSTR odd)
    // warp owns d slice [8*wid, 8*wid+8)
    ull oacc[4] = {0ull, 0ull, 0ull, 0ull};
    const float* Prow = Pbuf + lane * PSTR;

    #pragma unroll 1
    for (int v = 0; v < 8; ++v) {
        if (v == 7) cp_wait0(); else cp_wait1();
        __syncthreads();       // also publishes phase-3 Pbuf stores on v==0

        const float* vp = KV + (v & 1) * KHALF + wid * 8;
        const float* pp = Prow + v * KTILE;

        #pragma unroll 4
        for (int kk = 0; kk < KTILE; ++kk) {
            ull pdup = splat2(pp[kk]);
            ull v01, v23, v45, v67;
            lds_2x64(v01, v23, vp + kk * SKP);
            lds_2x64(v45, v67, vp + kk * SKP + 4);
            fma2(oacc[0], pdup, v01);
            fma2(oacc[1], pdup, v23);
            fma2(oacc[2], pdup, v45);
            fma2(oacc[3], pdup, v67);
        }

        __syncthreads();
        if (v + 2 < 8) {
            prefetch_tile(Vbh + (size_t)(v + 2) * KTILE * DD_, KV + (v & 1) * KHALF, tid);
            cp_commit();
        }
    }

    if (out_o) {
        float* orow = out_o + ((size_t)bh * LQ_ + q0 + lane) * DD_ + wid * 8;
        float2 a = upk2(oacc[0]), b = upk2(oacc[1]);
        float2 c = upk2(oacc[2]), d = upk2(oacc[3]);
        float4 f0 = {a.x, a.y, b.x, b.y};
        float4 f1 = {c.x, c.y, d.x, d.y};
        *(float4*)orow       = f0;
        *(float4*)(orow + 4) = f1;
    }
}

extern "C" void kernel_launch(void* const* d_in, const int* in_sizes, int n_in,
                              void* d_out, int out_size)
{
    const float* q  = (const float*)d_in[0];
    const float* k  = (const float*)d_in[1];
    const float* v  = (const float*)d_in[2];
    const int*   m  = (const int*)d_in[3];
    const float* qm = (const float*)d_in[4];

    const long long NO = (long long)BH_ * LQ_ * DD_;
    const long long NA = (long long)BH_ * LQ_ * LK_;

    float* out_o = nullptr;
    float* out_a = nullptr;
    if ((long long)out_size >= NO + NA) {
        out_o = (float*)d_out;
        out_a = (float*)d_out + NO;
    } else if ((long long)out_size == NA) {
        out_a = (float*)d_out;
    } else {
        out_o = (float*)d_out;
    }

    cudaFuncSetAttribute(attention_fused_kernel,
                         cudaFuncAttributeMaxDynamicSharedMemorySize, SMEM_BYTES);

    dim3 grid(LQ_ / TQ_, BH_);
    dim3 block(NT);
    attention_fused_kernel<<<grid, block, SMEM_BYTES>>>(q, k, v, m, qm, out_o, out_a);
}

// round 4
// speedup vs baseline: 1.8480x; 1.1877x over previous
#include <cuda_runtime.h>
#include <cstdint>

#define BH_   64
#define LQ_   1024
#define LK_   1024
#define DD_   64
#define TQ_   32
#define NT    256
#define KTILE 128
#define SKP   68      // K/V smem row stride
#define SQP   76      // Q smem row stride
#define PSTR  1028    // Pbuf row stride: 16B-aligned rows; phase-4 q-stride-1 bank stride 4
#define KHALF (KTILE*SKP)
#define SCR_QS 18     // phase-4 reduction scratch row stride (floats)

#define SMEM_FLOATS (TQ_*PSTR + TQ_*SQP + 2*KHALF + 32)
#define SMEM_BYTES  (SMEM_FLOATS*4)

typedef unsigned long long ull;

__device__ __forceinline__ void fma2(ull& d, ull a, ull b) {
    asm volatile("fma.rn.f32x2 %0, %1, %2, %0;" : "+l"(d) : "l"(a), "l"(b));
}
__device__ __forceinline__ void add2(ull& d, ull a) {
    asm volatile("add.rn.f32x2 %0, %0, %1;" : "+l"(d) : "l"(a));
}
__device__ __forceinline__ ull splat2(float x) {
    ull u; asm("mov.b64 %0, {%1, %1};" : "=l"(u) : "f"(x)); return u;
}
__device__ __forceinline__ float2 upk2(ull u) {
    float2 r; asm("mov.b64 {%0, %1}, %2;" : "=f"(r.x), "=f"(r.y) : "l"(u)); return r;
}
__device__ __forceinline__ void lds_2x64(ull& a, ull& b, const float* p) {
    uint32_t s = (uint32_t)__cvta_generic_to_shared(p);
    asm volatile("ld.shared.v2.b64 {%0, %1}, [%2];" : "=l"(a), "=l"(b) : "r"(s));
}
__device__ __forceinline__ void sts64(float* p, ull v) {
    uint32_t s = (uint32_t)__cvta_generic_to_shared(p);
    asm volatile("st.shared.b64 [%0], %1;" :: "r"(s), "l"(v));
}
__device__ __forceinline__ ull lds64(const float* p) {
    ull v; uint32_t s = (uint32_t)__cvta_generic_to_shared(p);
    asm volatile("ld.shared.b64 %0, [%1];" : "=l"(v) : "r"(s));
    return v;
}
__device__ __forceinline__ void cp16(float* dst, const float* src) {
    uint32_t s = (uint32_t)__cvta_generic_to_shared(dst);
    asm volatile("cp.async.cg.shared.global [%0], [%1], 16;" :: "r"(s), "l"(src));
}
__device__ __forceinline__ void cp_commit() { asm volatile("cp.async.commit_group;"); }
__device__ __forceinline__ void cp_wait0() { asm volatile("cp.async.wait_group 0;"); }
__device__ __forceinline__ void cp_wait1() { asm volatile("cp.async.wait_group 1;"); }

__device__ __forceinline__ void prefetch_tile(const float* __restrict__ g, float* s, int tid) {
    #pragma unroll
    for (int it = 0; it < 8; ++it) {
        int idx = tid + it * NT;
        int r   = idx >> 4;
        int c4  = idx & 15;
        cp16(s + r * SKP + c4 * 4, g + r * DD_ + c4 * 4);
    }
}

__global__ void __launch_bounds__(NT, 1)
attention_fused_kernel(const float* __restrict__ Qg,
                       const float* __restrict__ Kg,
                       const float* __restrict__ Vg,
                       const int*   __restrict__ Mg,
                       const float* __restrict__ QMg,
                       float* __restrict__ out_o,
                       float* __restrict__ out_a)
{
    extern __shared__ float smem[];
    float* Pbuf   = smem;                          // [32][PSTR]
    float* Qs     = smem + TQ_ * PSTR;             // [32][SQP]; reused as phase-4 scratch
    float* KV     = Qs + TQ_ * SQP;                // [2][KTILE][SKP]
    float* scales = KV + 2 * KHALF;                // [32]

    const int tid  = threadIdx.x;
    const int lane = tid & 31;
    const int wid  = tid >> 5;
    const int bh   = blockIdx.y;
    const int q0   = blockIdx.x * TQ_;

    const float* Qrow = Qg + ((size_t)bh * LQ_ + q0) * DD_;
    const float* Kbh  = Kg + (size_t)bh * LK_ * DD_;
    const float* Vbh  = Vg + (size_t)bh * LK_ * DD_;

    prefetch_tile(Kbh,                KV,         tid); cp_commit();
    prefetch_tile(Kbh + KTILE * DD_,  KV + KHALF, tid); cp_commit();

    // ---- load Q (scaled by 1/8) into swizzled smem ----
    #pragma unroll
    for (int it = 0; it < 2; ++it) {
        int idx = tid + it * NT;
        int r = idx >> 4;
        int c4 = idx & 15;
        float4 v = *(const float4*)(Qrow + r * DD_ + c4 * 4);
        v.x *= 0.125f; v.y *= 0.125f; v.z *= 0.125f; v.w *= 0.125f;
        *(float4*)(&Qs[r * SQP + ((r >> 3) & 1) * 8 + c4 * 4]) = v;
    }

    // ---------------- phase 2: S = (Q/8) K^T into Pbuf ----------------
    const int qh = wid >> 2;
    const int kg = wid & 3;
    const int ql = lane >> 3;
    const int kl = lane & 7;
    const int qbase = qh * 16 + ql * 4;
    const int qswz  = ((qbase >> 3) & 1) * 8;
    const int krow0 = kg * 32 + kl;

    #pragma unroll 1
    for (int t = 0; t < 8; ++t) {
        cp_wait1();
        __syncthreads();

        const float* Kt = KV + (t & 1) * KHALF;

        ull acc[4][4];
        #pragma unroll
        for (int i = 0; i < 4; ++i)
            #pragma unroll
            for (int j = 0; j < 4; ++j) acc[i][j] = 0ull;

        #pragma unroll 4
        for (int d = 0; d < DD_; d += 4) {
            ull q01[4], q23[4], k01[4], k23[4];
            #pragma unroll
            for (int i = 0; i < 4; ++i)
                lds_2x64(q01[i], q23[i], Qs + (qbase + i) * SQP + qswz + d);
            #pragma unroll
            for (int j = 0; j < 4; ++j)
                lds_2x64(k01[j], k23[j], Kt + (krow0 + j * 8) * SKP + d);
            #pragma unroll
            for (int i = 0; i < 4; ++i)
                #pragma unroll
                for (int j = 0; j < 4; ++j) {
                    fma2(acc[i][j], q01[i], k01[j]);
                    fma2(acc[i][j], q23[i], k23[j]);
                }
        }

        #pragma unroll
        for (int i = 0; i < 4; ++i) {
            float* prow = Pbuf + (qbase + i) * PSTR + t * KTILE + krow0;
            #pragma unroll
            for (int j = 0; j < 4; ++j) {
                float2 f = upk2(acc[i][j]);
                prow[j * 8] = f.x + f.y;
            }
        }

        __syncthreads();
        if (t + 2 < 8) {
            prefetch_tile(Kbh + (size_t)(t + 2) * KTILE * DD_, KV + (t & 1) * KHALF, tid);
        } else {
            prefetch_tile(Vbh + (size_t)(t + 2 - 8) * KTILE * DD_, KV + (t & 1) * KHALF, tid);
        }
        cp_commit();
    }
    // (loop's trailing __syncthreads published all Pbuf scores)

    // ---------------- phase 3: mask + softmax; store exp; scale deferred ----------------
    // warp w owns rows 4w..4w+3; row is register-resident: 8 float4 chunks per lane
    #pragma unroll 1
    for (int i = 0; i < 4; ++i) {
        const int q = wid * 4 + i;
        float* pr = Pbuf + q * PSTR;
        const int4* mrow = (const int4*)(Mg + ((size_t)bh * LQ_ + q0 + q) * LK_);

        float4 pv[8];
        float mx = -3.0e38f;
        #pragma unroll
        for (int c = 0; c < 8; ++c) {
            int k4 = c * 32 + lane;
            float4 v = *(float4*)(pr + k4 * 4);
            int4 m = mrow[k4];
            v.x = (m.x == 0) ? -1.0e9f : v.x;
            v.y = (m.y == 0) ? -1.0e9f : v.y;
            v.z = (m.z == 0) ? -1.0e9f : v.z;
            v.w = (m.w == 0) ? -1.0e9f : v.w;
            pv[c] = v;
            mx = fmaxf(mx, fmaxf(fmaxf(v.x, v.y), fmaxf(v.z, v.w)));
        }
        #pragma unroll
        for (int o = 16; o > 0; o >>= 1)
            mx = fmaxf(mx, __shfl_xor_sync(0xffffffffu, mx, o));

        float sum = 0.f;
        #pragma unroll
        for (int c = 0; c < 8; ++c) {
            float4 v = pv[c];
            v.x = __expf(v.x - mx);
            v.y = __expf(v.y - mx);
            v.z = __expf(v.z - mx);
            v.w = __expf(v.w - mx);
            pv[c] = v;
            sum += (v.x + v.y) + (v.z + v.w);
            int k4 = c * 32 + lane;
            *(float4*)(pr + k4 * 4) = v;          // unscaled exp back to Pbuf
        }
        #pragma unroll
        for (int o = 16; o > 0; o >>= 1)
            sum += __shfl_xor_sync(0xffffffffu, sum, o);

        const float sc = QMg[(size_t)bh * LQ_ + q0 + q] / sum;
        if (lane == 0) scales[q] = sc;

        if (out_a) {
            float* arow = out_a + ((size_t)bh * LQ_ + q0 + q) * LK_;
            #pragma unroll
            for (int c = 0; c < 8; ++c) {
                int k4 = c * 32 + lane;
                float4 v = pv[c];
                v.x *= sc; v.y *= sc; v.z *= sc; v.w *= sc;
                *(float4*)(arow + k4 * 4) = v;
            }
        }
    }

    // ---------------- phase 4: O = P @ V (register-tiled) ----------------
    // warp = (dgg 0..3, kh 0..1); lane = (ql 0..7, dl 0..3)
    // thread tile: q in {ql + 8i}, d = dgg*16 + dl*4 + {0..3}; k-half via kh (interleaved blocks)
    const int dgg = wid >> 1;
    const int kh  = wid & 1;
    const int ql4 = lane >> 2;       // 0..7
    const int dl4 = lane & 3;        // 0..3
    const int dof = dgg * 16 + dl4 * 4;

    ull acc[4][2];
    #pragma unroll
    for (int i = 0; i < 4; ++i) { acc[i][0] = 0ull; acc[i][1] = 0ull; }

    #pragma unroll 1
    for (int t = 0; t < 8; ++t) {
        if (t == 7) cp_wait0(); else cp_wait1();
        __syncthreads();   // t==0 also publishes phase-3 Pbuf/scales

        const float* Vt = KV + (t & 1) * KHALF + dof;

        #pragma unroll 4
        for (int blk = 0; blk < 16; ++blk) {
            const int kloc = (blk * 2 + kh) * 4;       // 0..124
            const int k0   = t * KTILE + kloc;

            float4 pvv[4];
            #pragma unroll
            for (int i = 0; i < 4; ++i)
                pvv[i] = *(float4*)(Pbuf + (ql4 + 8 * i) * PSTR + k0);

            ull v01[4], v23[4];
            #pragma unroll
            for (int kk = 0; kk < 4; ++kk)
                lds_2x64(v01[kk], v23[kk], Vt + (kloc + kk) * SKP);

            #pragma unroll
            for (int kk = 0; kk < 4; ++kk) {
                #pragma unroll
                for (int i = 0; i < 4; ++i) {
                    float p = (kk == 0) ? pvv[i].x : (kk == 1) ? pvv[i].y
                            : (kk == 2) ? pvv[i].z : pvv[i].w;
                    ull ps = splat2(p);
                    fma2(acc[i][0], ps, v01[kk]);
                    fma2(acc[i][1], ps, v23[kk]);
                }
            }
        }

        __syncthreads();
        if (t + 2 < 8) {
            prefetch_tile(Vbh + (size_t)(t + 2) * KTILE * DD_, KV + (t & 1) * KHALF, tid);
            cp_commit();
        }
    }

    // kh reduction through scratch (Qs region is dead now)
    float* scr = Qs;   // layout: [dgg][q:32][SCR_QS]
    if (kh == 1) {
        #pragma unroll
        for (int i = 0; i < 4; ++i) {
            float* p = scr + dgg * (32 * SCR_QS) + (ql4 + 8 * i) * SCR_QS + dl4 * 4;
            sts64(p,     acc[i][0]);
            sts64(p + 2, acc[i][1]);
        }
    }
    __syncthreads();
    if (kh == 0) {
        #pragma unroll
        for (int i = 0; i < 4; ++i) {
            const float* p = scr + dgg * (32 * SCR_QS) + (ql4 + 8 * i) * SCR_QS + dl4 * 4;
            add2(acc[i][0], lds64(p));
            add2(acc[i][1], lds64(p + 2));
        }
        if (out_o) {
            #pragma unroll
            for (int i = 0; i < 4; ++i) {
                const int q = ql4 + 8 * i;
                ull ss = splat2(scales[q]);
                ull r0 = 0ull, r1 = 0ull;
                fma2(r0, acc[i][0], ss);
                fma2(r1, acc[i][1], ss);
                float2 a = upk2(r0), b = upk2(r1);
                float4 o4 = {a.x, a.y, b.x, b.y};
                *(float4*)(out_o + ((size_t)bh * LQ_ + q0 + q) * DD_ + dof) = o4;
            }
        }
    }
}

extern "C" void kernel_launch(void* const* d_in, const int* in_sizes, int n_in,
                              void* d_out, int out_size)
{
    const float* q  = (const float*)d_in[0];
    const float* k  = (const float*)d_in[1];
    const float* v  = (const float*)d_in[2];
    const int*   m  = (const int*)d_in[3];
    const float* qm = (const float*)d_in[4];

    const long long NO = (long long)BH_ * LQ_ * DD_;
    const long long NA = (long long)BH_ * LQ_ * LK_;

    float* out_o = nullptr;
    float* out_a = nullptr;
    if ((long long)out_size >= NO + NA) {
        out_o = (float*)d_out;
        out_a = (float*)d_out + NO;
    } else if ((long long)out_size == NA) {
        out_a = (float*)d_out;
    } else {
        out_o = (float*)d_out;
    }

    cudaFuncSetAttribute(attention_fused_kernel,
                         cudaFuncAttributeMaxDynamicSharedMemorySize, SMEM_BYTES);

    dim3 grid(LQ_ / TQ_, BH_);
    dim3 block(NT);
    attention_fused_kernel<<<grid, block, SMEM_BYTES>>>(q, k, v, m, qm, out_o, out_a);
}

// round 6
// speedup vs baseline: 2.8946x; 1.5663x over previous
#include <cuda_runtime.h>
#include <cuda_bf16.h>
#include <cstdint>

#define BH_  64
#define LQ_  1024
#define LK_  1024
#define DD_  64
#define TQ_  32
#define NT   256
#define PSTR 1032            // Pbuf row stride (floats)
#define KROWB  144           // K/V smem row bytes (72 bf16: 64 data + 8 pad)
#define PBROWB 272           // P-bf16 smem row bytes (136 bf16: 128 data + 8 pad)
#define OFF_KV  132096       // after Pbuf (32*1032*4)
#define KVHALF  18432        // one 128x72 bf16 tile
#define KVBUFSZ 36864        // hi+lo
#define OFF_U   (OFF_KV + 2*KVBUFSZ)   // 205824: union{Q hi/lo | P hi/lo}
#define SM_TOTAL (OFF_U + 17408)       // 223232 bytes

__device__ __nv_bfloat16 g_QH[BH_*LQ_*DD_];
__device__ __nv_bfloat16 g_QL[BH_*LQ_*DD_];
__device__ __nv_bfloat16 g_KH[BH_*LK_*DD_];
__device__ __nv_bfloat16 g_KL[BH_*LK_*DD_];
__device__ __nv_bfloat16 g_VH[BH_*LK_*DD_];
__device__ __nv_bfloat16 g_VL[BH_*LK_*DD_];

__device__ __forceinline__ uint32_t s2u(const void* p) {
    uint32_t a;
    asm("{.reg .u64 t; cvta.to.shared.u64 t, %1; cvt.u32.u64 %0, t;}" : "=r"(a) : "l"(p));
    return a;
}
__device__ __forceinline__ void lm4(uint32_t* r, uint32_t addr) {
    asm volatile("ldmatrix.sync.aligned.m8n8.x4.shared.b16 {%0,%1,%2,%3}, [%4];"
                 : "=r"(r[0]), "=r"(r[1]), "=r"(r[2]), "=r"(r[3]) : "r"(addr));
}
__device__ __forceinline__ void lm4t(uint32_t* r, uint32_t addr) {
    asm volatile("ldmatrix.sync.aligned.m8n8.x4.trans.shared.b16 {%0,%1,%2,%3}, [%4];"
                 : "=r"(r[0]), "=r"(r[1]), "=r"(r[2]), "=r"(r[3]) : "r"(addr));
}
__device__ __forceinline__ void mma16816(float* c, const uint32_t* a, uint32_t b0, uint32_t b1) {
    asm volatile("mma.sync.aligned.m16n8k16.row.col.f32.bf16.bf16.f32 "
                 "{%0,%1,%2,%3}, {%4,%5,%6,%7}, {%8,%9}, {%0,%1,%2,%3};"
                 : "+f"(c[0]), "+f"(c[1]), "+f"(c[2]), "+f"(c[3])
                 : "r"(a[0]), "r"(a[1]), "r"(a[2]), "r"(a[3]), "r"(b0), "r"(b1));
}
__device__ __forceinline__ void cp16(char* dst, const void* src) {
    uint32_t s = s2u(dst);
    asm volatile("cp.async.cg.shared.global [%0], [%1], 16;" :: "r"(s), "l"(src));
}
__device__ __forceinline__ void cp_commit() { asm volatile("cp.async.commit_group;"); }
__device__ __forceinline__ void cp_wait0() { asm volatile("cp.async.wait_group 0;"); }
__device__ __forceinline__ void cp_wait1() { asm volatile("cp.async.wait_group 1;"); }

__device__ __forceinline__ uint32_t pack_hi2(float a, float b) {
    __nv_bfloat162 h = __halves2bfloat162(__float2bfloat16_rn(a), __float2bfloat16_rn(b));
    return *(uint32_t*)&h;
}
__device__ __forceinline__ uint32_t pack_lo2(float a, float b) {
    float ra = a - __bfloat162float(__float2bfloat16_rn(a));
    float rb = b - __bfloat162float(__float2bfloat16_rn(b));
    __nv_bfloat162 l = __halves2bfloat162(__float2bfloat16_rn(ra), __float2bfloat16_rn(rb));
    return *(uint32_t*)&l;
}

// ---------------- kernel 1: fp32 -> bf16 hi/lo splits ----------------
__global__ void __launch_bounds__(NT) cvt_kernel(const float* __restrict__ Q,
                                                 const float* __restrict__ K,
                                                 const float* __restrict__ V)
{
    const int which = blockIdx.y;
    const float* src = (which == 0) ? Q : (which == 1) ? K : V;
    __nv_bfloat16* dh = (which == 0) ? g_QH : (which == 1) ? g_KH : g_VH;
    __nv_bfloat16* dl = (which == 0) ? g_QL : (which == 1) ? g_KL : g_VL;
    const float sc = (which == 0) ? 0.125f : 1.0f;

    size_t i = ((size_t)blockIdx.x * NT + threadIdx.x) * 4;
    float4 f = *(const float4*)(src + i);
    f.x *= sc; f.y *= sc; f.z *= sc; f.w *= sc;
    uint2 h, l;
    h.x = pack_hi2(f.x, f.y); h.y = pack_hi2(f.z, f.w);
    l.x = pack_lo2(f.x, f.y); l.y = pack_lo2(f.z, f.w);
    *(uint2*)(dh + i) = h;
    *(uint2*)(dl + i) = l;
}

// load one 128-row bf16 hi/lo tile pair into a KV buffer
__device__ __forceinline__ void pf_kv(const __nv_bfloat16* __restrict__ gh,
                                      const __nv_bfloat16* __restrict__ gl,
                                      char* buf, int tid)
{
    #pragma unroll
    for (int it = 0; it < 4; ++it) {
        int idx = tid + it * NT;          // 0..1023
        int r = idx >> 3, c = idx & 7;
        cp16(buf + r * KROWB + c * 16,          (const char*)(gh + r * DD_) + c * 16);
        cp16(buf + KVHALF + r * KROWB + c * 16, (const char*)(gl + r * DD_) + c * 16);
    }
}

// ---------------- kernel 2: fused attention ----------------
__global__ void __launch_bounds__(NT, 1)
attn_kernel(const int* __restrict__ Mg, const float* __restrict__ QMg,
            float* __restrict__ out_o, float* __restrict__ out_a)
{
    extern __shared__ char smem[];
    float* Pbuf  = (float*)smem;
    char*  kvb   = smem + OFF_KV;
    char*  ubase = smem + OFF_U;

    const int tid  = threadIdx.x;
    const int lane = tid & 31;
    const int wid  = tid >> 5;
    const int bh   = blockIdx.y;
    const int q0   = blockIdx.x * TQ_;

    const size_t qoff = ((size_t)bh * LQ_ + q0) * DD_;
    const size_t koff = (size_t)bh * LK_ * DD_;

    // ---- prefetch Q (group 0, with K0) and K0/K1 ----
    {
        int r = tid >> 3, c = tid & 7;    // 256 chunks per half, 1 per thread
        cp16(ubase + r * KROWB + c * 16,        (const char*)(g_QH + qoff + r * DD_) + c * 16);
        cp16(ubase + 4608 + r * KROWB + c * 16, (const char*)(g_QL + qoff + r * DD_) + c * 16);
    }
    pf_kv(g_KH + koff, g_KL + koff, kvb, tid); cp_commit();
    pf_kv(g_KH + koff + 128 * DD_, g_KL + koff + 128 * DD_, kvb + KVBUFSZ, tid); cp_commit();

    // ================ phase 2: S = (Q/8)K^T -> Pbuf ================
    const int qh2 = wid >> 2, kg = wid & 3;
    const int q0w = qh2 * 16, kb0 = kg * 32;

    uint32_t aH[4][4], aL[4][4];

    #pragma unroll 1
    for (int t = 0; t < 8; ++t) {
        cp_wait1();
        __syncthreads();

        if (t == 0) {
            const uint32_t uH = s2u(ubase), uL = uH + 4608;
            const int arow = q0w + (lane & 15);
            #pragma unroll
            for (int ds = 0; ds < 4; ++ds) {
                const int acol = ds * 16 + ((lane >> 4) & 1) * 8;
                lm4(aH[ds], uH + arow * KROWB + acol * 2);
                lm4(aL[ds], uL + arow * KROWB + acol * 2);
            }
        }

        const uint32_t sH = s2u(kvb + (t & 1) * KVBUFSZ);
        const uint32_t sL = sH + KVHALF;

        float acc[4][4];
        #pragma unroll
        for (int j = 0; j < 4; ++j)
            #pragma unroll
            for (int e = 0; e < 4; ++e) acc[j][e] = 0.f;

        #pragma unroll
        for (int ds = 0; ds < 4; ++ds) {
            const int d0 = ds * 16;
            #pragma unroll
            for (int nb2 = 0; nb2 < 2; ++nb2) {
                const int brow = kb0 + nb2 * 16 + ((lane >> 4) & 1) * 8 + (lane & 7);
                const int bcol = d0 + ((lane >> 3) & 1) * 8;
                uint32_t bH[4], bL[4];
                lm4(bH, sH + brow * KROWB + bcol * 2);
                lm4(bL, sL + brow * KROWB + bcol * 2);
                float* c0 = acc[nb2 * 2];
                float* c1 = acc[nb2 * 2 + 1];
                mma16816(c0, aH[ds], bH[0], bH[1]);
                mma16816(c0, aH[ds], bL[0], bL[1]);
                mma16816(c0, aL[ds], bH[0], bH[1]);
                mma16816(c1, aH[ds], bH[2], bH[3]);
                mma16816(c1, aH[ds], bL[2], bL[3]);
                mma16816(c1, aL[ds], bH[2], bH[3]);
            }
        }

        // writeback scores
        const int srow = q0w + (lane >> 2);
        #pragma unroll
        for (int j = 0; j < 4; ++j) {
            const int col = t * 128 + kb0 + j * 8 + 2 * (lane & 3);
            *(float2*)&Pbuf[srow * PSTR + col]       = make_float2(acc[j][0], acc[j][1]);
            *(float2*)&Pbuf[(srow + 8) * PSTR + col] = make_float2(acc[j][2], acc[j][3]);
        }

        __syncthreads();
        if (t + 2 < 8) {
            pf_kv(g_KH + koff + (size_t)(t + 2) * 128 * DD_,
                  g_KL + koff + (size_t)(t + 2) * 128 * DD_, kvb + (t & 1) * KVBUFSZ, tid);
        } else {
            pf_kv(g_VH + koff + (size_t)(t - 6) * 128 * DD_,
                  g_VL + koff + (size_t)(t - 6) * 128 * DD_, kvb + (t & 1) * KVBUFSZ, tid);
        }
        cp_commit();
    }

    // ================ phase 3: mask + softmax (scaled p into Pbuf + out_a) ================
    #pragma unroll 1
    for (int i = 0; i < 4; ++i) {
        const int q = wid * 4 + i;
        float* pr = Pbuf + q * PSTR;
        const int4* mrow = (const int4*)(Mg + ((size_t)bh * LQ_ + q0 + q) * LK_);

        float4 pv[8];
        float mx = -3.0e38f;
        #pragma unroll
        for (int c = 0; c < 8; ++c) {
            int k4 = c * 32 + lane;
            float4 v = *(float4*)(pr + k4 * 4);
            int4 m = mrow[k4];
            v.x = (m.x == 0) ? -1.0e9f : v.x;
            v.y = (m.y == 0) ? -1.0e9f : v.y;
            v.z = (m.z == 0) ? -1.0e9f : v.z;
            v.w = (m.w == 0) ? -1.0e9f : v.w;
            pv[c] = v;
            mx = fmaxf(mx, fmaxf(fmaxf(v.x, v.y), fmaxf(v.z, v.w)));
        }
        #pragma unroll
        for (int o = 16; o > 0; o >>= 1)
            mx = fmaxf(mx, __shfl_xor_sync(0xffffffffu, mx, o));

        float sum = 0.f;
        #pragma unroll
        for (int c = 0; c < 8; ++c) {
            float4 v = pv[c];
            v.x = __expf(v.x - mx); v.y = __expf(v.y - mx);
            v.z = __expf(v.z - mx); v.w = __expf(v.w - mx);
            pv[c] = v;
            sum += (v.x + v.y) + (v.z + v.w);
        }
        #pragma unroll
        for (int o = 16; o > 0; o >>= 1)
            sum += __shfl_xor_sync(0xffffffffu, sum, o);

        const float sc = QMg[(size_t)bh * LQ_ + q0 + q] / sum;
        float* arow = out_a ? (out_a + ((size_t)bh * LQ_ + q0 + q) * LK_) : nullptr;
        #pragma unroll
        for (int c = 0; c < 8; ++c) {
            int k4 = c * 32 + lane;
            float4 v = pv[c];
            v.x *= sc; v.y *= sc; v.z *= sc; v.w *= sc;
            *(float4*)(pr + k4 * 4) = v;
            if (arow) *(float4*)(arow + k4 * 4) = v;
        }
    }

    // ================ phase 4: O = P @ V ================
    const int dblk = wid >> 1, qh4 = wid & 1;
    const int q0o = qh4 * 16, n0 = dblk * 16;
    const uint32_t pH = s2u(ubase), pL = pH + 8704;

    float oa[2][4];
    #pragma unroll
    for (int j = 0; j < 2; ++j)
        #pragma unroll
        for (int e = 0; e < 4; ++e) oa[j][e] = 0.f;

    #pragma unroll 1
    for (int t = 0; t < 8; ++t) {
        if (t == 7) cp_wait0(); else cp_wait1();
        __syncthreads();                    // V(t) ready; also separates prior mma from Pbf overwrite

        // convert P tile (32 x 128) -> bf16 hi/lo
        {
            const int r = tid >> 3, c16 = (tid & 7) * 16;
            const float* src = Pbuf + r * PSTR + t * 128 + c16;
            float4 f0 = *(const float4*)(src);
            float4 f1 = *(const float4*)(src + 4);
            float4 f2 = *(const float4*)(src + 8);
            float4 f3 = *(const float4*)(src + 12);
            uint4 hA, hB, lA, lB;
            hA.x = pack_hi2(f0.x, f0.y); hA.y = pack_hi2(f0.z, f0.w);
            hA.z = pack_hi2(f1.x, f1.y); hA.w = pack_hi2(f1.z, f1.w);
            hB.x = pack_hi2(f2.x, f2.y); hB.y = pack_hi2(f2.z, f2.w);
            hB.z = pack_hi2(f3.x, f3.y); hB.w = pack_hi2(f3.z, f3.w);
            lA.x = pack_lo2(f0.x, f0.y); lA.y = pack_lo2(f0.z, f0.w);
            lA.z = pack_lo2(f1.x, f1.y); lA.w = pack_lo2(f1.z, f1.w);
            lB.x = pack_lo2(f2.x, f2.y); lB.y = pack_lo2(f2.z, f2.w);
            lB.z = pack_lo2(f3.x, f3.y); lB.w = pack_lo2(f3.z, f3.w);
            char* dh = ubase + r * PBROWB + c16 * 2;
            char* dl = ubase + 8704 + r * PBROWB + c16 * 2;
            *(uint4*)dh = hA; *(uint4*)(dh + 16) = hB;
            *(uint4*)dl = lA; *(uint4*)(dl + 16) = lB;
        }
        __syncthreads();

        const uint32_t vH = s2u(kvb + (t & 1) * KVBUFSZ);
        const uint32_t vL = vH + KVHALF;

        #pragma unroll
        for (int ks = 0; ks < 8; ++ks) {
            const int k0 = ks * 16;
            uint32_t a4H[4], a4L[4];
            const int arow = q0o + (lane & 15);
            const int acol = k0 + ((lane >> 4) & 1) * 8;
            lm4(a4H, pH + arow * PBROWB + acol * 2);
            lm4(a4L, pL + arow * PBROWB + acol * 2);

            uint32_t b4H[4], b4L[4];
            const int vrow = k0 + ((lane >> 3) & 1) * 8 + (lane & 7);
            const int vcol = n0 + ((lane >> 4) & 1) * 8;
            lm4t(b4H, vH + vrow * KROWB + vcol * 2);
            lm4t(b4L, vL + vrow * KROWB + vcol * 2);

            mma16816(oa[0], a4H, b4H[0], b4H[1]);
            mma16816(oa[0], a4H, b4L[0], b4L[1]);
            mma16816(oa[0], a4L, b4H[0], b4H[1]);
            mma16816(oa[1], a4H, b4H[2], b4H[3]);
            mma16816(oa[1], a4H, b4L[2], b4L[3]);
            mma16816(oa[1], a4L, b4H[2], b4H[3]);
        }

        __syncthreads();
        if (t + 2 < 8) {
            pf_kv(g_VH + koff + (size_t)(t + 2) * 128 * DD_,
                  g_VL + koff + (size_t)(t + 2) * 128 * DD_, kvb + (t & 1) * KVBUFSZ, tid);
            cp_commit();
        }
    }

    if (out_o) {
        const int row0 = q0 + q0o + (lane >> 2);
        #pragma unroll
        for (int j = 0; j < 2; ++j) {
            const int col = n0 + j * 8 + 2 * (lane & 3);
            float* o0 = out_o + ((size_t)bh * LQ_ + row0) * DD_ + col;
            *(float2*)o0 = make_float2(oa[j][0], oa[j][1]);
            *(float2*)(o0 + 8 * DD_) = make_float2(oa[j][2], oa[j][3]);
        }
    }
}

extern "C" void kernel_launch(void* const* d_in, const int* in_sizes, int n_in,
                              void* d_out, int out_size)
{
    const float* q  = (const float*)d_in[0];
    const float* k  = (const float*)d_in[1];
    const float* v  = (const float*)d_in[2];
    const int*   m  = (const int*)d_in[3];
    const float* qm = (const float*)d_in[4];

    const long long NO = (long long)BH_ * LQ_ * DD_;
    const long long NA = (long long)BH_ * LQ_ * LK_;

    float* out_o = nullptr;
    float* out_a = nullptr;
    if ((long long)out_size >= NO + NA) {
        out_o = (float*)d_out;
        out_a = (float*)d_out + NO;
    } else if ((long long)out_size == NA) {
        out_a = (float*)d_out;
    } else {
        out_o = (float*)d_out;
    }

    cvt_kernel<<<dim3((BH_*LQ_*DD_) / (NT * 4), 3), NT>>>(q, k, v);

    cudaFuncSetAttribute(attn_kernel,
                         cudaFuncAttributeMaxDynamicSharedMemorySize, SM_TOTAL);
    attn_kernel<<<dim3(LQ_ / TQ_, BH_), NT, SM_TOTAL>>>(m, qm, out_o, out_a);
}

// round 7
// speedup vs baseline: 3.1462x; 1.0869x over previous
#include <cuda_runtime.h>
#include <cuda_bf16.h>
#include <cstdint>

#define BH_  64
#define LQ_  1024
#define LK_  1024
#define DD_  64
#define TQ_  32
#define NT   512
#define PSTR_B 4144          // Pbuf row bytes: fp32 S (4096) / bf16 hi@0 + lo@2064 planes
#define LO_OFF 2064
#define KROWB  144           // K/V smem row bytes (72 bf16)
#define OFF_KV  (TQ_*PSTR_B)             // 132608
#define KVHALF  18432
#define KVBUFSZ 36864
#define OFF_U   (OFF_KV + 2*KVBUFSZ)     // 206336: Q hi/lo (phase2) / dead after
#define SM_TOTAL (OFF_U + 9216)          // 215552

__device__ __nv_bfloat16 g_QH[BH_*LQ_*DD_];
__device__ __nv_bfloat16 g_QL[BH_*LQ_*DD_];
__device__ __nv_bfloat16 g_KH[BH_*LK_*DD_];
__device__ __nv_bfloat16 g_KL[BH_*LK_*DD_];
__device__ __nv_bfloat16 g_VH[BH_*LK_*DD_];
__device__ __nv_bfloat16 g_VL[BH_*LK_*DD_];

__device__ __forceinline__ uint32_t s2u(const void* p) {
    uint32_t a;
    asm("{.reg .u64 t; cvta.to.shared.u64 t, %1; cvt.u32.u64 %0, t;}" : "=r"(a) : "l"(p));
    return a;
}
__device__ __forceinline__ void lm4(uint32_t* r, uint32_t addr) {
    asm volatile("ldmatrix.sync.aligned.m8n8.x4.shared.b16 {%0,%1,%2,%3}, [%4];"
                 : "=r"(r[0]), "=r"(r[1]), "=r"(r[2]), "=r"(r[3]) : "r"(addr));
}
__device__ __forceinline__ void lm4t(uint32_t* r, uint32_t addr) {
    asm volatile("ldmatrix.sync.aligned.m8n8.x4.trans.shared.b16 {%0,%1,%2,%3}, [%4];"
                 : "=r"(r[0]), "=r"(r[1]), "=r"(r[2]), "=r"(r[3]) : "r"(addr));
}
__device__ __forceinline__ void mma16816(float* c, const uint32_t* a, uint32_t b0, uint32_t b1) {
    asm volatile("mma.sync.aligned.m16n8k16.row.col.f32.bf16.bf16.f32 "
                 "{%0,%1,%2,%3}, {%4,%5,%6,%7}, {%8,%9}, {%0,%1,%2,%3};"
                 : "+f"(c[0]), "+f"(c[1]), "+f"(c[2]), "+f"(c[3])
                 : "r"(a[0]), "r"(a[1]), "r"(a[2]), "r"(a[3]), "r"(b0), "r"(b1));
}
__device__ __forceinline__ void cp16(char* dst, const void* src) {
    uint32_t s = s2u(dst);
    asm volatile("cp.async.cg.shared.global [%0], [%1], 16;" :: "r"(s), "l"(src));
}
__device__ __forceinline__ void cp_commit() { asm volatile("cp.async.commit_group;"); }
__device__ __forceinline__ void cp_wait0() { asm volatile("cp.async.wait_group 0;"); }
__device__ __forceinline__ void cp_wait1() { asm volatile("cp.async.wait_group 1;"); }

__device__ __forceinline__ uint32_t pack_hi2(float a, float b) {
    __nv_bfloat162 h = __halves2bfloat162(__float2bfloat16_rn(a), __float2bfloat16_rn(b));
    return *(uint32_t*)&h;
}
__device__ __forceinline__ uint32_t pack_lo2(float a, float b) {
    float ra = a - __bfloat162float(__float2bfloat16_rn(a));
    float rb = b - __bfloat162float(__float2bfloat16_rn(b));
    __nv_bfloat162 l = __halves2bfloat162(__float2bfloat16_rn(ra), __float2bfloat16_rn(rb));
    return *(uint32_t*)&l;
}

// ---------------- kernel 1: fp32 -> bf16 hi/lo splits ----------------
__global__ void __launch_bounds__(256) cvt_kernel(const float* __restrict__ Q,
                                                  const float* __restrict__ K,
                                                  const float* __restrict__ V)
{
    const int which = blockIdx.y;
    const float* src = (which == 0) ? Q : (which == 1) ? K : V;
    __nv_bfloat16* dh = (which == 0) ? g_QH : (which == 1) ? g_KH : g_VH;
    __nv_bfloat16* dl = (which == 0) ? g_QL : (which == 1) ? g_KL : g_VL;
    const float sc = (which == 0) ? 0.125f : 1.0f;

    size_t i = ((size_t)blockIdx.x * 256 + threadIdx.x) * 4;
    float4 f = *(const float4*)(src + i);
    f.x *= sc; f.y *= sc; f.z *= sc; f.w *= sc;
    uint2 h, l;
    h.x = pack_hi2(f.x, f.y); h.y = pack_hi2(f.z, f.w);
    l.x = pack_lo2(f.x, f.y); l.y = pack_lo2(f.z, f.w);
    *(uint2*)(dh + i) = h;
    *(uint2*)(dl + i) = l;
}

__device__ __forceinline__ void pf_kv(const __nv_bfloat16* __restrict__ gh,
                                      const __nv_bfloat16* __restrict__ gl,
                                      char* buf, int tid)
{
    #pragma unroll
    for (int it = 0; it < 2; ++it) {
        int idx = tid + it * NT;          // 0..1023
        int r = idx >> 3, c = idx & 7;
        cp16(buf + r * KROWB + c * 16,          (const char*)(gh + r * DD_) + c * 16);
        cp16(buf + KVHALF + r * KROWB + c * 16, (const char*)(gl + r * DD_) + c * 16);
    }
}

// ---------------- kernel 2: fused attention ----------------
__global__ void __launch_bounds__(NT, 1)
attn_kernel(const int* __restrict__ Mg, const float* __restrict__ QMg,
            float* __restrict__ out_o, float* __restrict__ out_a)
{
    extern __shared__ char smem[];
    char* kvb   = smem + OFF_KV;
    char* ubase = smem + OFF_U;

    const int tid  = threadIdx.x;
    const int lane = tid & 31;
    const int wid  = tid >> 5;            // 0..15
    const int bh   = blockIdx.y;
    const int q0   = blockIdx.x * TQ_;

    const size_t qoff = ((size_t)bh * LQ_ + q0) * DD_;
    const size_t koff = (size_t)bh * LK_ * DD_;

    // ---- prefetch Q hi/lo (tid<256: hi; tid>=256: lo) + K0/K1 ----
    {
        int pl = tid >> 8, t2 = tid & 255;
        int r = t2 >> 3, c = t2 & 7;
        const __nv_bfloat16* src = pl ? (g_QL + qoff) : (g_QH + qoff);
        cp16(ubase + pl * 4608 + r * KROWB + c * 16, (const char*)(src + r * DD_) + c * 16);
    }
    pf_kv(g_KH + koff, g_KL + koff, kvb, tid); cp_commit();
    pf_kv(g_KH + koff + 128 * DD_, g_KL + koff + 128 * DD_, kvb + KVBUFSZ, tid); cp_commit();

    // ================ phase 2: S = (Q/8)K^T -> Pbuf (fp32) ================
    const int qh2 = wid >> 3, kg = wid & 7;
    const int q0w = qh2 * 16, kb0 = kg * 16;

    uint32_t aH[4][4], aL[4][4];

    #pragma unroll 1
    for (int t = 0; t < 8; ++t) {
        cp_wait1();
        __syncthreads();

        if (t == 0) {
            const uint32_t uH = s2u(ubase), uL = uH + 4608;
            const int arow = q0w + (lane & 15);
            #pragma unroll
            for (int ds = 0; ds < 4; ++ds) {
                const int acol = ds * 16 + ((lane >> 4) & 1) * 8;
                lm4(aH[ds], uH + arow * KROWB + acol * 2);
                lm4(aL[ds], uL + arow * KROWB + acol * 2);
            }
        }

        const uint32_t sH = s2u(kvb + (t & 1) * KVBUFSZ);
        const uint32_t sL = sH + KVHALF;

        float accA[2][4], accB[2][4];
        #pragma unroll
        for (int j = 0; j < 2; ++j)
            #pragma unroll
            for (int e = 0; e < 4; ++e) { accA[j][e] = 0.f; accB[j][e] = 0.f; }

        const int brow = kb0 + ((lane >> 4) & 1) * 8 + (lane & 7);
        #pragma unroll
        for (int ds = 0; ds < 4; ++ds) {
            const int bcol = ds * 16 + ((lane >> 3) & 1) * 8;
            uint32_t bH[4], bL[4];
            lm4(bH, sH + brow * KROWB + bcol * 2);
            lm4(bL, sL + brow * KROWB + bcol * 2);
            mma16816(accA[0], aH[ds], bH[0], bH[1]);
            mma16816(accB[0], aH[ds], bL[0], bL[1]);
            mma16816(accA[0], aL[ds], bH[0], bH[1]);
            mma16816(accA[1], aH[ds], bH[2], bH[3]);
            mma16816(accB[1], aH[ds], bL[2], bL[3]);
            mma16816(accA[1], aL[ds], bH[2], bH[3]);
        }

        const int srow = q0w + (lane >> 2);
        float* p0 = (float*)(smem + srow * PSTR_B);
        float* p1 = (float*)(smem + (srow + 8) * PSTR_B);
        #pragma unroll
        for (int j = 0; j < 2; ++j) {
            const int col = t * 128 + kb0 + j * 8 + 2 * (lane & 3);
            *(float2*)(p0 + col) = make_float2(accA[j][0] + accB[j][0], accA[j][1] + accB[j][1]);
            *(float2*)(p1 + col) = make_float2(accA[j][2] + accB[j][2], accA[j][3] + accB[j][3]);
        }

        __syncthreads();
        if (t + 2 < 8) {
            pf_kv(g_KH + koff + (size_t)(t + 2) * 128 * DD_,
                  g_KL + koff + (size_t)(t + 2) * 128 * DD_, kvb + (t & 1) * KVBUFSZ, tid);
        } else {
            pf_kv(g_VH + koff + (size_t)(t - 6) * 128 * DD_,
                  g_VL + koff + (size_t)(t - 6) * 128 * DD_, kvb + (t & 1) * KVBUFSZ, tid);
        }
        cp_commit();
    }

    // ================ phase 3: mask + softmax; write bf16 hi/lo planes + out_a ================
    #pragma unroll 1
    for (int i = 0; i < 2; ++i) {
        const int q = wid * 2 + i;
        char* rowb = smem + q * PSTR_B;
        float* pr = (float*)rowb;
        const int4* mrow = (const int4*)(Mg + ((size_t)bh * LQ_ + q0 + q) * LK_);

        float4 pv[8];
        float mx = -3.0e38f;
        #pragma unroll
        for (int c = 0; c < 8; ++c) {
            int k4 = c * 32 + lane;
            float4 v = *(float4*)(pr + k4 * 4);
            int4 m = mrow[k4];
            v.x = (m.x == 0) ? -1.0e9f : v.x;
            v.y = (m.y == 0) ? -1.0e9f : v.y;
            v.z = (m.z == 0) ? -1.0e9f : v.z;
            v.w = (m.w == 0) ? -1.0e9f : v.w;
            pv[c] = v;
            mx = fmaxf(mx, fmaxf(fmaxf(v.x, v.y), fmaxf(v.z, v.w)));
        }
        #pragma unroll
        for (int o = 16; o > 0; o >>= 1)
            mx = fmaxf(mx, __shfl_xor_sync(0xffffffffu, mx, o));

        float sum = 0.f;
        #pragma unroll
        for (int c = 0; c < 8; ++c) {
            float4 v = pv[c];
            v.x = __expf(v.x - mx); v.y = __expf(v.y - mx);
            v.z = __expf(v.z - mx); v.w = __expf(v.w - mx);
            pv[c] = v;
            sum += (v.x + v.y) + (v.z + v.w);
        }
        #pragma unroll
        for (int o = 16; o > 0; o >>= 1)
            sum += __shfl_xor_sync(0xffffffffu, sum, o);

        const float sc = QMg[(size_t)bh * LQ_ + q0 + q] / sum;
        float* arow = out_a ? (out_a + ((size_t)bh * LQ_ + q0 + q) * LK_) : nullptr;
        #pragma unroll
        for (int c = 0; c < 8; ++c) {
            int k4 = c * 32 + lane;
            float4 v = pv[c];
            v.x *= sc; v.y *= sc; v.z *= sc; v.w *= sc;
            uint2 h, l;
            h.x = pack_hi2(v.x, v.y); h.y = pack_hi2(v.z, v.w);
            l.x = pack_lo2(v.x, v.y); l.y = pack_lo2(v.z, v.w);
            *(uint2*)(rowb + 8 * k4)          = h;
            *(uint2*)(rowb + LO_OFF + 8 * k4) = l;
            if (arow) *(float4*)(arow + k4 * 4) = v;
        }
    }

    // ================ phase 4: O = P @ V (lm4 direct from Pbuf planes) ================
    const int dblk = wid >> 2;           // 0..3
    const int qh4  = (wid >> 1) & 1;     // 0..1
    const int kh   = wid & 1;            // k-half split
    const int q0o = qh4 * 16, n0 = dblk * 16;
    const uint32_t pbase = s2u(smem);

    float oaA[2][4], oaB[2][4];
    #pragma unroll
    for (int j = 0; j < 2; ++j)
        #pragma unroll
        for (int e = 0; e < 4; ++e) { oaA[j][e] = 0.f; oaB[j][e] = 0.f; }

    const int arow = q0o + (lane & 15);
    const int vrl  = ((lane >> 3) & 1) * 8 + (lane & 7);
    const int vcol = n0 + ((lane >> 4) & 1) * 8;

    #pragma unroll 1
    for (int t = 0; t < 8; ++t) {
        if (t == 7) cp_wait0(); else cp_wait1();
        __syncthreads();                 // t==0 also publishes phase-3 planes

        const uint32_t vH = s2u(kvb + (t & 1) * KVBUFSZ);
        const uint32_t vL = vH + KVHALF;

        #pragma unroll
        for (int ks = 0; ks < 4; ++ks) {
            const int k0 = kh * 64 + ks * 16;
            uint32_t a4H[4], a4L[4];
            const uint32_t ab = pbase + arow * PSTR_B +
                                2 * (t * 128 + k0 + ((lane >> 4) & 1) * 8);
            lm4(a4H, ab);
            lm4(a4L, ab + LO_OFF);

            uint32_t b4H[4], b4L[4];
            const uint32_t vb = (k0 + vrl) * KROWB + vcol * 2;
            lm4t(b4H, vH + vb);
            lm4t(b4L, vL + vb);

            mma16816(oaA[0], a4H, b4H[0], b4H[1]);
            mma16816(oaB[0], a4H, b4L[0], b4L[1]);
            mma16816(oaA[0], a4L, b4H[0], b4H[1]);
            mma16816(oaA[1], a4H, b4H[2], b4H[3]);
            mma16816(oaB[1], a4H, b4L[2], b4L[3]);
            mma16816(oaA[1], a4L, b4H[2], b4H[3]);
        }

        __syncthreads();
        if (t + 2 < 8) {
            pf_kv(g_VH + koff + (size_t)(t + 2) * 128 * DD_,
                  g_VL + koff + (size_t)(t + 2) * 128 * DD_, kvb + (t & 1) * KVBUFSZ, tid);
            cp_commit();
        }
    }

    // ---- kh reduction (scratch in dead KV region) + output ----
    float* scr = (float*)kvb;            // [8 groups][16][20]
    const int grp = dblk * 2 + qh4;
    __syncthreads();
    if (kh == 1) {
        #pragma unroll
        for (int j = 0; j < 2; ++j) {
            const int c = n0 - n0 + j * 8 + 2 * (lane & 3);   // local col 0..15
            float* s0 = scr + grp * 320 + (lane >> 2) * 20 + c;
            float* s1 = scr + grp * 320 + ((lane >> 2) + 8) * 20 + c;
            *(float2*)s0 = make_float2(oaA[j][0] + oaB[j][0], oaA[j][1] + oaB[j][1]);
            *(float2*)s1 = make_float2(oaA[j][2] + oaB[j][2], oaA[j][3] + oaB[j][3]);
        }
    }
    __syncthreads();
    if (kh == 0 && out_o) {
        const int row0 = q0 + q0o + (lane >> 2);
        #pragma unroll
        for (int j = 0; j < 2; ++j) {
            const int cl = j * 8 + 2 * (lane & 3);
            float2 s0 = *(float2*)(scr + grp * 320 + (lane >> 2) * 20 + cl);
            float2 s1 = *(float2*)(scr + grp * 320 + ((lane >> 2) + 8) * 20 + cl);
            float* o0 = out_o + ((size_t)bh * LQ_ + row0) * DD_ + n0 + cl;
            *(float2*)o0 = make_float2(oaA[j][0] + oaB[j][0] + s0.x,
                                       oaA[j][1] + oaB[j][1] + s0.y);
            *(float2*)(o0 + 8 * DD_) = make_float2(oaA[j][2] + oaB[j][2] + s1.x,
                                                   oaA[j][3] + oaB[j][3] + s1.y);
        }
    }
}

extern "C" void kernel_launch(void* const* d_in, const int* in_sizes, int n_in,
                              void* d_out, int out_size)
{
    const float* q  = (const float*)d_in[0];
    const float* k  = (const float*)d_in[1];
    const float* v  = (const float*)d_in[2];
    const int*   m  = (const int*)d_in[3];
    const float* qm = (const float*)d_in[4];

    const long long NO = (long long)BH_ * LQ_ * DD_;
    const long long NA = (long long)BH_ * LQ_ * LK_;

    float* out_o = nullptr;
    float* out_a = nullptr;
    if ((long long)out_size >= NO + NA) {
        out_o = (float*)d_out;
        out_a = (float*)d_out + NO;
    } else if ((long long)out_size == NA) {
        out_a = (float*)d_out;
    } else {
        out_o = (float*)d_out;
    }

    cvt_kernel<<<dim3((BH_*LQ_*DD_) / (256 * 4), 3), 256>>>(q, k, v);

    cudaFuncSetAttribute(attn_kernel,
                         cudaFuncAttributeMaxDynamicSharedMemorySize, SM_TOTAL);
    attn_kernel<<<dim3(LQ_ / TQ_, BH_), NT, SM_TOTAL>>>(m, qm, out_o, out_a);
}